// round 1
// baseline (speedup 1.0000x reference)
#include <cuda_runtime.h>

// FiringRateModel: T-step scalar-feedback linear recurrence, B independent chains.
// Parallelization: 4 lanes per chain (R=4), 16 neurons per lane, packed f32x2 math.
// Restructured so the per-step serial path is only the scalar phi() chain:
//   p(t) = D*u(t-1) + c_t*A          (wide, independent of f(t-1))
//   z(t) = sum(p(t)) + f(t-1)*SB     (scalar fma)
//   f(t) = max(0, 200 - 400/(1+2^(K*poly(z - gb'))))   K = 2*log2(e)
//   u(t) = p(t) + f(t-1)*B           (wide, folded into next p)

#define TPB 128

typedef unsigned long long u64p;

__device__ __forceinline__ u64p pk2(float lo, float hi) {
    u64p r;
    asm("mov.b64 %0, {%1,%2};" : "=l"(r) : "r"(__float_as_uint(lo)), "r"(__float_as_uint(hi)));
    return r;
}
__device__ __forceinline__ void upk2(u64p v, float &lo, float &hi) {
    unsigned int l, h;
    asm("mov.b64 {%0,%1}, %2;" : "=r"(l), "=r"(h) : "l"(v));
    lo = __uint_as_float(l); hi = __uint_as_float(h);
}
__device__ __forceinline__ u64p f2fma(u64p a, u64p b, u64p c) {
    u64p d;
    asm("fma.rn.f32x2 %0, %1, %2, %3;" : "=l"(d) : "l"(a), "l"(b), "l"(c));
    return d;
}
__device__ __forceinline__ u64p f2mul(u64p a, u64p b) {
    u64p d;
    asm("mul.rn.f32x2 %0, %1, %2;" : "=l"(d) : "l"(a), "l"(b));
    return d;
}
__device__ __forceinline__ u64p f2add(u64p a, u64p b) {
    u64p d;
    asm("add.rn.f32x2 %0, %1, %2;" : "=l"(d) : "l"(a), "l"(b));
    return d;
}
__device__ __forceinline__ float ex2a(float x) {
    float r; asm("ex2.approx.f32 %0, %1;" : "=f"(r) : "f"(x)); return r;
}
__device__ __forceinline__ float rcpa(float x) {
    float r; asm("rcp.approx.f32 %0, %1;" : "=f"(r) : "f"(x)); return r;
}

__global__ void __launch_bounds__(TPB)
fr_kernel(const float* __restrict__ cur,   // [T, B]
          const float* __restrict__ fs0,   // [B]
          const float* __restrict__ av,    // [N]
          const float* __restrict__ bv,    // [N]
          const float* __restrict__ wv,    // [N]
          const float* __restrict__ dsv,   // [N]
          const float* __restrict__ pc,    // [6]
          const float* __restrict__ gbp,   // [1]
          float* __restrict__ out,         // [T, B]
          int T, int B)
{
    int tid = blockIdx.x * TPB + threadIdx.x;
    int chain = tid >> 2;        // one chain per 4 lanes
    int r = tid & 3;             // lane within chain group
    if (chain >= B) return;
    int nb = r * 16;             // neuron base for this lane (16 neurons)

    // phi() constants: fold 1/100 into coeffs/state, 2*log2(e) into polynomial.
    const float K = 2.885390081777927f;  // 2*log2(e)
    float gb = gbp[0] * 0.01f;
    float C0 = K * pc[0] * pc[0], C1 = K * pc[1] * pc[1], C2 = K * pc[2] * pc[2];
    float C3 = K * pc[3] * pc[3], C4 = K * pc[4] * pc[4], C5 = K * pc[5] * pc[5];

    // Per-lane coefficients (8 packed pairs = 16 neurons)
    u64p D[8], A2[8], Bc[8], P[8];
    float sbp = 0.f;
    #pragma unroll
    for (int j = 0; j < 8; j++) {
        int n0 = nb + 2 * j;
        float w0 = wv[n0], w1 = wv[n0 + 1];
        float d0 = 1.f - dsv[n0], d1 = 1.f - dsv[n0 + 1];
        float a0 = av[n0] * w0 * 0.01f, a1 = av[n0 + 1] * w1 * 0.01f;
        float b0 = 10.f * bv[n0] * w0, b1 = 10.f * bv[n0 + 1] * w1;  // 1000/100 = 10
        D[j]  = pk2(d0, d1);
        A2[j] = pk2(a0, a1);
        Bc[j] = pk2(b0, b1);
        sbp += b0 + b1;
    }
    // SB = sum over all 64 neurons of Bc (butterfly across the 4 chain lanes)
    sbp += __shfl_xor_sync(0xffffffffu, sbp, 1);
    sbp += __shfl_xor_sync(0xffffffffu, sbp, 2);
    const float SB = sbp;

    float f = fs0[chain];        // f(-1)

    const float* curp = cur + chain;
    float* outp = out + chain;

    // Prologue: p(0) = c_0 * A  (u(-1) = 0); base(0) = sum(p(0)) - gb
    float base;
    {
        float c0v = curp[0];
        u64p c2 = pk2(c0v, c0v);
        u64p acc0 = 0ull, acc1 = 0ull;
        #pragma unroll
        for (int j = 0; j < 8; j++) {
            P[j] = f2mul(A2[j], c2);
            if (j & 1) acc1 = f2add(acc1, P[j]); else acc0 = f2add(acc0, P[j]);
        }
        float lo, hi; upk2(f2add(acc0, acc1), lo, hi);
        float s = lo + hi;
        s += __shfl_xor_sync(0xffffffffu, s, 1);
        s += __shfl_xor_sync(0xffffffffu, s, 2);
        base = s - gb;
    }

    // Prefetch ring: cb[i] holds c_{t+1} for upcoming iterations (distance 4)
    float cb[4];
    #pragma unroll
    for (int i = 0; i < 4; i++) {
        int tt = (1 + i < T) ? (1 + i) : (T - 1);
        cb[i] = curp[(size_t)tt * B];
    }

    for (int t = 0; t < T; t += 4) {
        #pragma unroll
        for (int k = 0; k < 4; k++) {
            int tk = t + k;
            float cnext = cb[k];
            int tp = tk + 5; if (tp > T - 1) tp = T - 1;
            cb[k] = curp[(size_t)tp * B];             // refill ring (MLP=4)

            // ---- serial scalar path: f(t) = phi(base + f(t-1)*SB) ----
            float x = fmaf(f, SB, base);
            float q = fmaf(C5, x, C4);
            q = fmaf(q, x, C3);
            q = fmaf(q, x, C2);
            q = fmaf(q, x, C1);
            q = fmaf(q, x, C0);                        // q = K * poly(x)
            float e = ex2a(q);                         // e = exp(2*poly)
            float fn = fmaf(rcpa(e + 1.f), -400.f, 200.f);
            fn = fmaxf(fn, 0.f);                       // f(t)

            // ---- wide path (uses f(t-1), c_{t+1}; independent of fn) ----
            u64p f2 = pk2(f, f);
            u64p c2 = pk2(cnext, cnext);
            u64p acc0 = 0ull, acc1 = 0ull;
            #pragma unroll
            for (int j = 0; j < 8; j++) {
                u64p u  = f2fma(Bc[j], f2, P[j]);              // u(t) = p(t) + f(t-1)*B
                u64p pn = f2fma(A2[j], c2, f2mul(D[j], u));    // p(t+1) = D*u(t) + c_{t+1}*A
                P[j] = pn;
                if (j & 1) acc1 = f2add(acc1, pn); else acc0 = f2add(acc0, pn);
            }
            float lo, hi; upk2(f2add(acc0, acc1), lo, hi);
            float s = lo + hi;
            s += __shfl_xor_sync(0xffffffffu, s, 1);
            s += __shfl_xor_sync(0xffffffffu, s, 2);
            base = s - gb;                             // base(t+1)

            if (r == 0) outp[(size_t)tk * B] = fn;
            f = fn;
        }
    }
}

extern "C" void kernel_launch(void* const* d_in, const int* in_sizes, int n_in,
                              void* d_out, int out_size) {
    const float* cur = (const float*)d_in[0];   // currents [T*B]
    const float* fs0 = (const float*)d_in[1];   // [B]
    const float* av  = (const float*)d_in[2];   // [N]
    const float* bv  = (const float*)d_in[3];   // [N]
    const float* wv  = (const float*)d_in[4];   // [N,1]
    const float* dsv = (const float*)d_in[5];   // [N]
    const float* pc  = (const float*)d_in[6];   // [DEG+1]
    const float* gbp = (const float*)d_in[7];   // scalar

    int B = in_sizes[1];
    int T = in_sizes[0] / B;

    int threads = B * 4;                        // 4 lanes per chain
    int blocks = (threads + TPB - 1) / TPB;
    fr_kernel<<<blocks, TPB>>>(cur, fs0, av, bv, wv, dsv, pc, gbp,
                               (float*)d_out, T, B);
}

// round 4
// speedup vs baseline: 1.4945x; 1.4945x over previous
#include <cuda_runtime.h>

// FiringRateModel: T-step scalar-feedback linear recurrence, B independent chains.
//
// Reformulated with pre-multiplied state y = D∘u (u = v.*w/100):
//   z(t)   = sum(y(t-1)) + c_t*SA + f(t-1)*SB          (scalar; sum from PREV step)
//   f(t)   = max(0, 200 - 400/(1 + 2^(K*poly(z))))     (== relu(200*tanh(poly)))
//   y(t)   = D∘y(t-1) + c_t*DA + f(t-1)*DB             (wide, 3 f2-ops/pair)
//   S(t)   = sum(y(t))  -> tree + 1 shfl, consumed at t+1 (off critical path)
//
// c_t*SA - gb is precomputed at prefetch time (8 steps ahead), so the serial
// path is: S -> add -> fma(f) -> Estrin -> ex2 -> rcp -> fma -> max.
// K = 2*log2(e) folded into the squared polynomial coefficients.
//
// R=2 lanes per chain, 16 f32x2 pairs per lane, 1 shfl. 16384 threads = 512
// warps; TPB=128, grid=128 -> 1 warp per SMSP.

#define TPB 128

typedef unsigned long long u64p;

__device__ __forceinline__ u64p pk2(float lo, float hi) {
    u64p r;
    asm("mov.b64 %0, {%1,%2};" : "=l"(r) : "r"(__float_as_uint(lo)), "r"(__float_as_uint(hi)));
    return r;
}
__device__ __forceinline__ void upk2(u64p v, float &lo, float &hi) {
    unsigned int l, h;
    asm("mov.b64 {%0,%1}, %2;" : "=r"(l), "=r"(h) : "l"(v));
    lo = __uint_as_float(l); hi = __uint_as_float(h);
}
__device__ __forceinline__ u64p f2fma(u64p a, u64p b, u64p c) {
    u64p d;
    asm("fma.rn.f32x2 %0, %1, %2, %3;" : "=l"(d) : "l"(a), "l"(b), "l"(c));
    return d;
}
__device__ __forceinline__ u64p f2mul(u64p a, u64p b) {
    u64p d;
    asm("mul.rn.f32x2 %0, %1, %2;" : "=l"(d) : "l"(a), "l"(b));
    return d;
}
__device__ __forceinline__ u64p f2add(u64p a, u64p b) {
    u64p d;
    asm("add.rn.f32x2 %0, %1, %2;" : "=l"(d) : "l"(a), "l"(b));
    return d;
}
__device__ __forceinline__ float ex2a(float x) {
    float r; asm("ex2.approx.f32 %0, %1;" : "=f"(r) : "f"(x)); return r;
}
__device__ __forceinline__ float rcpa(float x) {
    float r; asm("rcp.approx.f32 %0, %1;" : "=f"(r) : "f"(x)); return r;
}

__global__ void __launch_bounds__(TPB, 1)
fr_kernel(const float* __restrict__ cur,   // [T, B]
          const float* __restrict__ fs0,   // [B]
          const float* __restrict__ av,    // [N]
          const float* __restrict__ bv,    // [N]
          const float* __restrict__ wv,    // [N]
          const float* __restrict__ dsv,   // [N]
          const float* __restrict__ pc,    // [6]
          const float* __restrict__ gbp,   // [1]
          float* __restrict__ out,         // [T, B]
          int T, int B)
{
    int tid = blockIdx.x * TPB + threadIdx.x;
    int chain = tid >> 1;        // one chain per 2 lanes
    int r = tid & 1;
    if (chain >= B) return;
    int nb = r * 32;             // 32 neurons = 16 packed pairs per lane

    // Polynomial coefficients, squared per reference, with K = 2*log2(e)
    // folded in so q = K*poly(x) and tanh = 1 - 2/(1+2^q).
    const float K = 2.885390081777927f;
    float C0 = K * pc[0] * pc[0], C1 = K * pc[1] * pc[1], C2 = K * pc[2] * pc[2];
    float C3 = K * pc[3] * pc[3], C4 = K * pc[4] * pc[4], C5 = K * pc[5] * pc[5];
    float gb = gbp[0] * 0.01f;

    // Per-lane constants. u = v.*w/100: A' = a*w/100, B' = 10*b*w, D = 1-ds.
    // Pre-multiplied: DA = D∘A', DB = D∘B'.
    u64p D[16], DA[16], DB[16], Y[16];
    float sap = 0.f, sbp = 0.f;
    #pragma unroll
    for (int j = 0; j < 16; j++) {
        int n0 = nb + 2 * j;
        float w0 = wv[n0],            w1 = wv[n0 + 1];
        float d0 = 1.f - dsv[n0],     d1 = 1.f - dsv[n0 + 1];
        float a0 = av[n0] * w0 * 0.01f, a1 = av[n0 + 1] * w1 * 0.01f;
        float b0 = 10.f * bv[n0] * w0,  b1 = 10.f * bv[n0 + 1] * w1;
        D[j]  = pk2(d0, d1);
        DA[j] = pk2(d0 * a0, d1 * a1);
        DB[j] = pk2(d0 * b0, d1 * b1);
        Y[j]  = 0ull;
        sap += a0 + a1;
        sbp += b0 + b1;
    }
    sap += __shfl_xor_sync(0xffffffffu, sap, 1);
    sbp += __shfl_xor_sync(0xffffffffu, sbp, 1);
    const float SA = sap, SB = sbp;

    float f = fs0[chain];        // f(-1)
    float S = 0.f;               // sum(y(-1)) = 0  (v0 = 0)

    const float* cp = cur + chain;         // c_t reader (initial ring fill)
    const float* lp = cp + (size_t)8 * B;  // prefetch pointer -> c_{t+8}
    float* op = out + chain;

    // Prefetch rings: cb[i] = c_i (raw, for wide path),
    //                 cs[i] = c_i*SA - gb (for serial path, hoisted)
    float cb[8], cs[8];
    #pragma unroll
    for (int i = 0; i < 8; i++) {
        cb[i] = cp[(size_t)i * B];
        cs[i] = fmaf(cb[i], SA, -gb);
    }

    // One recurrence step. craw = c_t, cpre = c_t*SA - gb.
    // Computes f(t), updates Y -> y(t), S -> sum(y(t)).
    #define FR_STEP(craw, cpre)                                                \
    {                                                                          \
        /* serial scalar path: x = S(t-1) + (c*SA - gb) + f(t-1)*SB */         \
        float base = S + (cpre);                                               \
        float x = fmaf(f, SB, base);                                           \
        float x2 = x * x;                                                      \
        float x4 = x2 * x2;                                                    \
        float e01 = fmaf(C1, x, C0);                                           \
        float e23 = fmaf(C3, x, C2);                                           \
        float e45 = fmaf(C5, x, C4);                                           \
        float q = fmaf(x2, e23, e01);                                          \
        q = fmaf(x4, e45, q);                          /* q = K*poly(x) */     \
        float e = ex2a(q);                                                     \
        float fn = fmaf(rcpa(e + 1.f), -400.f, 200.f);                         \
        fn = fmaxf(fn, 0.f);                                                   \
        /* wide path (uses f(t-1), c_t; independent of fn) */                  \
        u64p c2 = pk2((craw), (craw));                                         \
        u64p f2 = pk2(f, f);                                                   \
        _Pragma("unroll")                                                      \
        for (int j = 0; j < 16; j++) {                                         \
            u64p t1 = f2fma(DB[j], f2, f2mul(DA[j], c2));                      \
            Y[j] = f2fma(D[j], Y[j], t1);                                      \
        }                                                                      \
        /* reduce sum(y(t)) -> consumed NEXT step (off critical path) */       \
        u64p g0 = f2add(f2add(Y[0],  Y[1]),  f2add(Y[2],  Y[3]));              \
        u64p g1 = f2add(f2add(Y[4],  Y[5]),  f2add(Y[6],  Y[7]));              \
        u64p g2 = f2add(f2add(Y[8],  Y[9]),  f2add(Y[10], Y[11]));             \
        u64p g3 = f2add(f2add(Y[12], Y[13]), f2add(Y[14], Y[15]));             \
        u64p gt = f2add(f2add(g0, g1), f2add(g2, g3));                         \
        float lo, hi; upk2(gt, lo, hi);                                        \
        float s = lo + hi;                                                     \
        s += __shfl_xor_sync(0xffffffffu, s, 1);                               \
        S = s;                                                                 \
        if (r == 0) *op = fn;                                                  \
        op += B;                                                               \
        f = fn;                                                                \
    }

    // Main loop: steps [0, T-8), refill rings at distance 8
    for (int t = 0; t < T - 8; t += 8) {
        #pragma unroll
        for (int k = 0; k < 8; k++) {
            float craw = cb[k];
            float cpre = cs[k];
            float cnew = *lp; lp += B;
            cb[k] = cnew;
            cs[k] = fmaf(cnew, SA, -gb);
            FR_STEP(craw, cpre)
        }
    }
    // Epilogue: last 8 steps, no loads
    #pragma unroll
    for (int k = 0; k < 8; k++) {
        FR_STEP(cb[k], cs[k])
    }
    #undef FR_STEP
}

extern "C" void kernel_launch(void* const* d_in, const int* in_sizes, int n_in,
                              void* d_out, int out_size) {
    const float* cur = (const float*)d_in[0];   // currents [T*B]
    const float* fs0 = (const float*)d_in[1];   // [B]
    const float* av  = (const float*)d_in[2];   // [N]
    const float* bv  = (const float*)d_in[3];   // [N]
    const float* wv  = (const float*)d_in[4];   // [N,1]
    const float* dsv = (const float*)d_in[5];   // [N]
    const float* pc  = (const float*)d_in[6];   // [DEG+1]
    const float* gbp = (const float*)d_in[7];   // scalar

    int B = in_sizes[1];
    int T = in_sizes[0] / B;

    int threads = B * 2;                        // 2 lanes per chain
    int blocks = (threads + TPB - 1) / TPB;
    fr_kernel<<<blocks, TPB>>>(cur, fs0, av, bv, wv, dsv, pc, gbp,
                               (float*)d_out, T, B);
}

// round 5
// speedup vs baseline: 1.5895x; 1.0635x over previous
#include <cuda_runtime.h>

// FiringRateModel: T-step scalar-feedback linear recurrence, B independent chains.
//
// y = D∘u state (u = v.*w/100), pre-multiplied so the wide update is 3 ops/pair:
//   z(t)   = sum(y(t-1)) + c_t*SA + f(t-1)*SB          (scalar; sum from PREV step)
//   f(t)   = max(0, 200 - 400/(1 + 2^(K*poly(z))))     (== relu(200*tanh(poly)))
//   y(t)   = D∘y(t-1) + c_t*DA + f(t-1)*DB             (wide)
//   S(t)   = sum(y(t))  -> tree + 2 shfl, consumed at t+1 (off critical path)
//
// R=4 lanes per chain (8 f32x2 pairs per lane) -> 32768 threads = 1024 warps
// = 2 warps per SMSP: the second warp fills the serial-chain stall cycles
// (R=2 @ 1 warp/SMSP measured 300 cyc/step with issue only 32% -- latency-bound).

#define TPB 256

typedef unsigned long long u64p;

__device__ __forceinline__ u64p pk2(float lo, float hi) {
    u64p r;
    asm("mov.b64 %0, {%1,%2};" : "=l"(r) : "r"(__float_as_uint(lo)), "r"(__float_as_uint(hi)));
    return r;
}
__device__ __forceinline__ void upk2(u64p v, float &lo, float &hi) {
    unsigned int l, h;
    asm("mov.b64 {%0,%1}, %2;" : "=r"(l), "=r"(h) : "l"(v));
    lo = __uint_as_float(l); hi = __uint_as_float(h);
}
__device__ __forceinline__ u64p f2fma(u64p a, u64p b, u64p c) {
    u64p d;
    asm("fma.rn.f32x2 %0, %1, %2, %3;" : "=l"(d) : "l"(a), "l"(b), "l"(c));
    return d;
}
__device__ __forceinline__ u64p f2mul(u64p a, u64p b) {
    u64p d;
    asm("mul.rn.f32x2 %0, %1, %2;" : "=l"(d) : "l"(a), "l"(b));
    return d;
}
__device__ __forceinline__ u64p f2add(u64p a, u64p b) {
    u64p d;
    asm("add.rn.f32x2 %0, %1, %2;" : "=l"(d) : "l"(a), "l"(b));
    return d;
}
__device__ __forceinline__ float ex2a(float x) {
    float r; asm("ex2.approx.f32 %0, %1;" : "=f"(r) : "f"(x)); return r;
}
__device__ __forceinline__ float rcpa(float x) {
    float r; asm("rcp.approx.f32 %0, %1;" : "=f"(r) : "f"(x)); return r;
}

__global__ void __launch_bounds__(TPB, 1)
fr_kernel(const float* __restrict__ cur,   // [T, B]
          const float* __restrict__ fs0,   // [B]
          const float* __restrict__ av,    // [N]
          const float* __restrict__ bv,    // [N]
          const float* __restrict__ wv,    // [N]
          const float* __restrict__ dsv,   // [N]
          const float* __restrict__ pc,    // [6]
          const float* __restrict__ gbp,   // [1]
          float* __restrict__ out,         // [T, B]
          int T, int B)
{
    int tid = blockIdx.x * TPB + threadIdx.x;
    int chain = tid >> 2;        // one chain per 4 lanes
    int r = tid & 3;
    if (chain >= B) return;
    int nb = r * 16;             // 16 neurons = 8 packed pairs per lane

    // Polynomial coefficients, squared per reference, with K = 2*log2(e)
    // folded in so q = K*poly(x) and tanh = 1 - 2/(1+2^q).
    const float K = 2.885390081777927f;
    float C0 = K * pc[0] * pc[0], C1 = K * pc[1] * pc[1], C2 = K * pc[2] * pc[2];
    float C3 = K * pc[3] * pc[3], C4 = K * pc[4] * pc[4], C5 = K * pc[5] * pc[5];
    float gb = gbp[0] * 0.01f;

    // Per-lane constants. u = v.*w/100: A' = a*w/100, B' = 10*b*w, D = 1-ds.
    // Pre-multiplied: DA = D∘A', DB = D∘B'.
    u64p D[8], DA[8], DB[8], Y[8];
    float sap = 0.f, sbp = 0.f;
    #pragma unroll
    for (int j = 0; j < 8; j++) {
        int n0 = nb + 2 * j;
        float w0 = wv[n0],            w1 = wv[n0 + 1];
        float d0 = 1.f - dsv[n0],     d1 = 1.f - dsv[n0 + 1];
        float a0 = av[n0] * w0 * 0.01f, a1 = av[n0 + 1] * w1 * 0.01f;
        float b0 = 10.f * bv[n0] * w0,  b1 = 10.f * bv[n0 + 1] * w1;
        D[j]  = pk2(d0, d1);
        DA[j] = pk2(d0 * a0, d1 * a1);
        DB[j] = pk2(d0 * b0, d1 * b1);
        Y[j]  = 0ull;
        sap += a0 + a1;
        sbp += b0 + b1;
    }
    sap += __shfl_xor_sync(0xffffffffu, sap, 1);
    sap += __shfl_xor_sync(0xffffffffu, sap, 2);
    sbp += __shfl_xor_sync(0xffffffffu, sbp, 1);
    sbp += __shfl_xor_sync(0xffffffffu, sbp, 2);
    const float SA = sap, SB = sbp;

    float f = fs0[chain];        // f(-1)
    float S = 0.f;               // sum(y(-1)) = 0  (v0 = 0)

    const float* cp = cur + chain;         // c_t reader (initial ring fill)
    const float* lp = cp + (size_t)8 * B;  // prefetch pointer -> c_{t+8}
    float* op = out + chain;

    // Prefetch rings: cb[i] = c_i (raw, for wide path),
    //                 cs[i] = c_i*SA - gb (for serial path, hoisted)
    float cb[8], cs[8];
    #pragma unroll
    for (int i = 0; i < 8; i++) {
        cb[i] = cp[(size_t)i * B];
        cs[i] = fmaf(cb[i], SA, -gb);
    }

    // One recurrence step. craw = c_t, cpre = c_t*SA - gb.
    // Computes f(t), updates Y -> y(t), S -> sum(y(t)).
    #define FR_STEP(craw, cpre)                                                \
    {                                                                          \
        /* serial scalar path: x = S(t-1) + (c*SA - gb) + f(t-1)*SB */         \
        float base = S + (cpre);                                               \
        float x = fmaf(f, SB, base);                                           \
        float x2 = x * x;                                                      \
        float x4 = x2 * x2;                                                    \
        float e01 = fmaf(C1, x, C0);                                           \
        float e23 = fmaf(C3, x, C2);                                           \
        float e45 = fmaf(C5, x, C4);                                           \
        float q = fmaf(x2, e23, e01);                                          \
        q = fmaf(x4, e45, q);                          /* q = K*poly(x) */     \
        float e = ex2a(q);                                                     \
        float fn = fmaf(rcpa(e + 1.f), -400.f, 200.f);                         \
        fn = fmaxf(fn, 0.f);                                                   \
        /* wide path (uses f(t-1), c_t; independent of fn) */                  \
        u64p c2 = pk2((craw), (craw));                                         \
        u64p f2 = pk2(f, f);                                                   \
        _Pragma("unroll")                                                      \
        for (int j = 0; j < 8; j++) {                                          \
            u64p t1 = f2fma(DB[j], f2, f2mul(DA[j], c2));                      \
            Y[j] = f2fma(D[j], Y[j], t1);                                      \
        }                                                                      \
        /* reduce sum(y(t)) -> consumed NEXT step (off critical path) */       \
        u64p g0 = f2add(f2add(Y[0], Y[1]), f2add(Y[2], Y[3]));                 \
        u64p g1 = f2add(f2add(Y[4], Y[5]), f2add(Y[6], Y[7]));                 \
        u64p gt = f2add(g0, g1);                                               \
        float lo, hi; upk2(gt, lo, hi);                                        \
        float s = lo + hi;                                                     \
        s += __shfl_xor_sync(0xffffffffu, s, 1);                               \
        s += __shfl_xor_sync(0xffffffffu, s, 2);                               \
        S = s;                                                                 \
        if (r == 0) *op = fn;                                                  \
        op += B;                                                               \
        f = fn;                                                                \
    }

    // Main loop: steps [0, T-8), refill rings at distance 8
    for (int t = 0; t < T - 8; t += 8) {
        #pragma unroll
        for (int k = 0; k < 8; k++) {
            float craw = cb[k];
            float cpre = cs[k];
            float cnew = *lp; lp += B;
            cb[k] = cnew;
            cs[k] = fmaf(cnew, SA, -gb);
            FR_STEP(craw, cpre)
        }
    }
    // Epilogue: last 8 steps, no loads
    #pragma unroll
    for (int k = 0; k < 8; k++) {
        FR_STEP(cb[k], cs[k])
    }
    #undef FR_STEP
}

extern "C" void kernel_launch(void* const* d_in, const int* in_sizes, int n_in,
                              void* d_out, int out_size) {
    const float* cur = (const float*)d_in[0];   // currents [T*B]
    const float* fs0 = (const float*)d_in[1];   // [B]
    const float* av  = (const float*)d_in[2];   // [N]
    const float* bv  = (const float*)d_in[3];   // [N]
    const float* wv  = (const float*)d_in[4];   // [N,1]
    const float* dsv = (const float*)d_in[5];   // [N]
    const float* pc  = (const float*)d_in[6];   // [DEG+1]
    const float* gbp = (const float*)d_in[7];   // scalar

    int B = in_sizes[1];
    int T = in_sizes[0] / B;

    int threads = B * 4;                        // 4 lanes per chain
    int blocks = (threads + TPB - 1) / TPB;
    fr_kernel<<<blocks, TPB>>>(cur, fs0, av, bv, wv, dsv, pc, gbp,
                               (float*)d_out, T, B);
}